// round 6
// baseline (speedup 1.0000x reference)
#include <cuda_runtime.h>
#include <math.h>

#define N_NODE 200
#define N_HID  1500
#define N_BAT  20
#define N_IN   6
#define PADC   52          // padded column-block width (16B-aligned float4 blocks)

// ---------------- scratch (static device globals; no allocation) ----------------
__device__ float g_wl[N_NODE * N_NODE];
__device__ float g_rowsum[N_NODE];
__device__ float g_part[N_NODE];
__device__ float g_invnorm;
__device__ float g_ls[N_NODE * N_NODE];

// ---------------- prep: build l_s = w_n - diag(rowsum(w_n)) ----------------
__global__ void prep1_kernel(const float* __restrict__ sc, const float* __restrict__ wbb) {
    int r = blockIdx.x;
    int c = threadIdx.x;
    float wl = 0.f;
    if (c < N_NODE) {
        float w_rc = expf(wbb[r * N_NODE + c]) * sc[r * N_NODE + c];
        float w_cr = expf(wbb[c * N_NODE + r]) * sc[c * N_NODE + r];
        wl = log1pf(0.5f * (w_rc + w_cr));
        g_wl[r * N_NODE + c] = wl;
    }
    __shared__ float s1[256], s2[256];
    s1[threadIdx.x] = wl;
    s2[threadIdx.x] = wl * wl;
    __syncthreads();
    for (int s = 128; s > 0; s >>= 1) {
        if (threadIdx.x < s) {
            s1[threadIdx.x] += s1[threadIdx.x + s];
            s2[threadIdx.x] += s2[threadIdx.x + s];
        }
        __syncthreads();
    }
    if (threadIdx.x == 0) {
        g_rowsum[r] = s1[0];
        g_part[r]   = s2[0];
    }
}

__global__ void prep2_kernel() {
    __shared__ float s[256];
    int t = threadIdx.x;
    s[t] = (t < N_NODE) ? g_part[t] : 0.f;
    __syncthreads();
    for (int k = 128; k > 0; k >>= 1) {
        if (t < k) s[t] += s[t + k];
        __syncthreads();
    }
    if (t == 0) g_invnorm = 1.f / sqrtf(s[0]);
}

__global__ void prep3_kernel() {
    int r = blockIdx.x;
    int c = threadIdx.x;
    if (c < N_NODE) {
        float v = g_wl[r * N_NODE + c];
        if (c == r) v -= g_rowsum[r];
        g_ls[r * N_NODE + c] = v * g_invnorm;
    }
}

// ---------------- simulation helpers ----------------
__device__ __forceinline__ float h_tf_dev(float a, float b, float d, float z) {
    float u   = fmaf(a, z, -b);
    float num = 1e-5f + fabsf(u);
    float den = fmaf(1e-5f, d, fabsf(1.0f - __expf(-d * u)));
    return __fdividef(num, den);
}

__device__ __forceinline__ float tanh_pos(float y) {
    // y >= 1e-5; tanh(y) = (1 - e^{-2y}) / (1 + e^{-2y})
    float t = __expf(-2.f * y);
    return __fdividef(1.f - t, 1.f + t);
}

#define FMA2(acc, a, b) \
    asm("fma.rn.f32x2 %0, %1, %2, %0;" : "+l"(acc) : "l"(a), "l"(b))
#define ADD2(acc, a) \
    asm("add.rn.f32x2 %0, %0, %1;" : "+l"(acc) : "l"(a))

__global__ void __launch_bounds__(800, 1) sim_kernel(
    const float* __restrict__ ext,   // (200,1500,20,6)
    const float* __restrict__ hx,    // (200,6)
    float* __restrict__ out,         // (200,20)
    const float* gp, const float* gEEp, const float* gIEp,
    const float* gEIp, const float* stdp)
{
    __shared__ __align__(16) float Ebuf[2][4 * PADC];   // 2 x 208
    __shared__ __align__(16) float Acc4[4 * N_NODE];    // 4 partials per row

    const int tid = threadIdx.x;
    const int w   = tid >> 5;
    const int l   = tid & 31;
    const int row = w * 8 + (l & 7);        // 0..199 (matvec row of this lane)
    const int cbl = (l >> 3) * 50;          // logical col start
    const int pcb = (l >> 3) * PADC;        // physical col start (16B aligned)
    const int accIdx = (row << 2) | (l >> 3);   // partial slot

    // ---- load W slice into registers as 26 packed f32x2 pairs (pad -> 0) ----
    unsigned long long W2[PADC / 2];
#pragma unroll
    for (int j = 0; j < PADC / 2; j++) {
        int k0 = 2 * j, k1 = 2 * j + 1;
        float w0 = (k0 < 50) ? g_ls[row * N_NODE + cbl + k0] : 0.f;
        float w1 = (k1 < 50) ? g_ls[row * N_NODE + cbl + k1] : 0.f;
        asm("mov.b64 %0, {%1, %2};" : "=l"(W2[j]) : "f"(w0), "f"(w1));
    }

    const float gg   = *gp;
    const float cEE  = 0.001f + fmaxf(*gEEp, 0.f);
    const float cIE  = 0.001f + fmaxf(*gIEp, 0.f);
    const float cEI  = 0.001f + fmaxf(*gEIp, 0.f);
    const float s_in = 0.02f + fmaxf(*stdp, 0.f);
    const float nscl = 0.70710678118654752440f * s_in;  // sqrt(dt)*s_in
    const float ln066 = -0.41551544396166582194f;       // log(0.66)
    const float it0  = 0.5f / 0.98f;                    // dt / tau_0
    const float its  = 1.f / 0.65f;
    const float itf  = 1.f / 0.41f;
    const float irho = 1.f / 0.34f;

    // ---- per-node state lives only in threads tid < 200 ----
    float E = 0.f, I = 0.f, X = 0.f, F = 0.f, V = 0.f, Q = 0.f, vpow = 0.f;
    const bool tail = (tid < N_NODE);
    const int epos  = (tid / 50) * PADC + (tid % 50);   // padded write slot

    // zero both E buffers (pads must be exactly 0)
    for (int i = tid; i < 2 * 4 * PADC; i += 800)
        ((float*)Ebuf)[i] = 0.f;
    __syncthreads();

    if (tail) {
        E = hx[tid * 6 + 0];
        I = hx[tid * 6 + 1];
        X = hx[tid * 6 + 2];
        F = hx[tid * 6 + 3];
        V = hx[tid * 6 + 4];
        Q = hx[tid * 6 + 5];
        vpow = __expf(3.125f * __logf(V));   // V^(1/alpha)
        Ebuf[0][epos] = E;
    }
    __syncthreads();

    const size_t NSTR = (size_t)N_BAT * N_IN;          // float stride per h
    const float* nbase = ext + (size_t)tid * (N_HID * NSTR);

    float* curE = Ebuf[0];
    float* nxtE = Ebuf[1];

#pragma unroll 1
    for (int b = 0; b < N_BAT; b++) {
        const float* np = nbase + b * N_IN;            // (h=0, b)
        float nx = 0.f, ny = 0.f;
        if (tail) {                                    // exposed once per batch
            float2 t0 = *(const float2*)np;
            nx = t0.x; ny = t0.y;
        }
#pragma unroll 1
        for (int h = 0; h < N_HID; h++) {
            // ---- prefetch next step's noise (covered by phase A + tail) ----
            float pnx = 0.f, pny = 0.f;
            const float* npn = np + NSTR;
            if (tail && h + 1 < N_HID) {
                float2 t1 = *(const float2*)npn;
                pnx = t1.x; pny = t1.y;
            }

            // -------- phase A: matvec (all warps), 4 accumulators ----------
            unsigned long long a0 = 0ull, a1 = 0ull, a2 = 0ull, a3 = 0ull;
            const ulonglong2* Eb = reinterpret_cast<const ulonglong2*>(curE + pcb);
#pragma unroll
            for (int k = 0; k < PADC / 8; k++) {       // 6 iters -> 12 of 13
                ulonglong2 e0 = Eb[2 * k];
                ulonglong2 e1 = Eb[2 * k + 1];
                FMA2(a0, W2[4 * k],     e0.x);
                FMA2(a1, W2[4 * k + 1], e0.y);
                FMA2(a2, W2[4 * k + 2], e1.x);
                FMA2(a3, W2[4 * k + 3], e1.y);
            }
            {   // residual 13th float4 (k = 12)
                ulonglong2 e0 = Eb[12];
                FMA2(a0, W2[24], e0.x);
                FMA2(a1, W2[25], e0.y);
            }
            // packed combine: 3 f32x2 adds + single unpack (no shuffles)
            ADD2(a0, a1);
            ADD2(a2, a3);
            ADD2(a0, a2);
            float plo, phi;
            asm("mov.b64 {%0, %1}, %2;" : "=f"(plo), "=f"(phi) : "l"(a0));
            Acc4[accIdx] = plo + phi;                  // this lane's 50-col partial
            __syncthreads();                           // bar1: all partials ready

            // -------- phase B: tail threads only ---------------------------
            if (tail) {
                float4 p = *(const float4*)&Acc4[tid << 2];
                float acc = gg * ((p.x + p.y) + (p.z + p.w));
                float Eold = E, Iold = I;
                float IE = fmaxf(acc + fmaf(cEE, Eold, 0.32f) - cIE * Iold, 0.f);
                float II = fmaxf(fmaf(cEI, Eold, 0.224f) - Iold, 0.f);
                float rE = h_tf_dev(310.f, 125.f, 0.16f,  IE);
                float rI = h_tf_dev(615.f, 177.f, 0.087f, II);
                float En = Eold + 0.5f * fmaf(0.000641f * (1.f - Eold), rE, -0.01f * Eold)
                                + nscl * nx;
                float In = Iold + 0.5f * fmaf(0.001f, rI, -0.1f * Iold)
                                + nscl * ny;
                E = tanh_pos(1e-5f + fmaxf(En, 0.f));
                I = tanh_pos(1e-5f + fmaxf(In, 0.f));
                nxtE[epos] = E;

                // deferred hemodynamics for step h-1 (uses Eold); its issue
                // fills the MUFU/RCP bubbles of the E/I chain above.
                if (h > 0) {
                    X = X + 0.5f * (Eold - X * its - (F - 1.f) * itf);
                    F = F + 0.5f * X;
                    float Vn = fmaf(it0, F - vpow, V);
                    float vq = __expf(3.125f * __logf(Vn));
                    float qa = F * (1.f - __expf(__fdividef(ln066, F))) * irho;
                    float qb = __fdividef(Q * vq, Vn);
                    Q = fmaf(it0, qa - qb, Q);
                    V = Vn; vpow = vq;
                }
            }
            __syncthreads();                           // bar2: nxtE ready
            float* t2 = curE; curE = nxtE; nxtE = t2;
            nx = pnx; ny = pny; np = npn;
        }

        // -------- batch end: flush the lagging hemo step + emit BOLD --------
        if (tail) {
            float Eold = E;                            // E after step 1499
            X = X + 0.5f * (Eold - X * its - (F - 1.f) * itf);
            F = F + 0.5f * X;
            float Vn = fmaf(it0, F - vpow, V);
            float vq = __expf(3.125f * __logf(Vn));
            float qa = F * (1.f - __expf(__fdividef(ln066, F))) * irho;
            float qb = __fdividef(Q * vq, Vn);
            Q = fmaf(it0, qa - qb, Q);
            V = Vn; vpow = vq;

            float n2 = nbase[(size_t)(N_HID - 1) * NSTR + b * N_IN + 2];
            float bold = 0.02f * n2 +
                5.8823529411764705882f * (2.38f * (1.f - Q)
                                        + 2.f * (1.f - __fdividef(Q, V))
                                        + 0.48f * (1.f - V));
            out[tid * N_BAT + b] = bold;
        }
    }
}

// ---------------- launch ----------------
extern "C" void kernel_launch(void* const* d_in, const int* in_sizes, int n_in,
                              void* d_out, int out_size) {
    const float* ext  = (const float*)d_in[0];  // external (200,1500,20,6)
    const float* hx   = (const float*)d_in[1];  // hx (200,6)
    // d_in[2] = hE (unused by reference)
    const float* sc   = (const float*)d_in[3];  // sc (200,200)
    const float* wbb  = (const float*)d_in[4];  // w_bb (200,200)
    const float* gp   = (const float*)d_in[5];
    const float* gEE  = (const float*)d_in[6];
    const float* gIE  = (const float*)d_in[7];
    const float* gEI  = (const float*)d_in[8];
    const float* stdp = (const float*)d_in[9];
    float* out = (float*)d_out;

    prep1_kernel<<<N_NODE, 256>>>(sc, wbb);
    prep2_kernel<<<1, 256>>>();
    prep3_kernel<<<N_NODE, 256>>>();
    sim_kernel<<<1, 800>>>(ext, hx, out, gp, gEE, gIE, gEI, stdp);
}

// round 8
// speedup vs baseline: 1.6297x; 1.6297x over previous
#include <cuda_runtime.h>
#include <math.h>

#define N_NODE 200
#define N_HID  1500
#define N_BAT  20
#define N_IN   6
#define NTH    256          // 8 warps x 32
#define RS     234          // AccP class stride (bank-conflict-free, verified)

// ---------------- scratch (static device globals; no allocation) ----------------
__device__ float g_wl[N_NODE * N_NODE];
__device__ float g_rowsum[N_NODE];
__device__ float g_part[N_NODE];
__device__ float g_invnorm;
__device__ float g_ls[N_NODE * N_NODE];
// transposed noise: [hb = h*20+b][node][2]
__device__ float g_noise[(size_t)N_HID * N_BAT * N_NODE * 2];

// ---------------- prep: build l_s = w_n - diag(rowsum(w_n)) ----------------
__global__ void prep1_kernel(const float* __restrict__ sc, const float* __restrict__ wbb) {
    int r = blockIdx.x;
    int c = threadIdx.x;
    float wl = 0.f;
    if (c < N_NODE) {
        float w_rc = expf(wbb[r * N_NODE + c]) * sc[r * N_NODE + c];
        float w_cr = expf(wbb[c * N_NODE + r]) * sc[c * N_NODE + r];
        wl = log1pf(0.5f * (w_rc + w_cr));
        g_wl[r * N_NODE + c] = wl;
    }
    __shared__ float s1[256], s2[256];
    s1[threadIdx.x] = wl;
    s2[threadIdx.x] = wl * wl;
    __syncthreads();
    for (int s = 128; s > 0; s >>= 1) {
        if (threadIdx.x < s) {
            s1[threadIdx.x] += s1[threadIdx.x + s];
            s2[threadIdx.x] += s2[threadIdx.x + s];
        }
        __syncthreads();
    }
    if (threadIdx.x == 0) {
        g_rowsum[r] = s1[0];
        g_part[r]   = s2[0];
    }
}

__global__ void prep2_kernel() {
    __shared__ float s[256];
    int t = threadIdx.x;
    s[t] = (t < N_NODE) ? g_part[t] : 0.f;
    __syncthreads();
    for (int k = 128; k > 0; k >>= 1) {
        if (t < k) s[t] += s[t + k];
        __syncthreads();
    }
    if (t == 0) g_invnorm = 1.f / sqrtf(s[0]);
}

__global__ void prep3_kernel() {
    int r = blockIdx.x;
    int c = threadIdx.x;
    if (c < N_NODE) {
        float v = g_wl[r * N_NODE + c];
        if (c == r) v -= g_rowsum[r];
        g_ls[r * N_NODE + c] = v * g_invnorm;
    }
}

// ---------------- noise transpose: ext(node,h,b,k) -> g_noise(hb,node,2) ----------
__global__ void transpose_noise_kernel(const float* __restrict__ ext) {
    __shared__ float2 tile[32][33];
    int hb0 = blockIdx.x * 32;
    int n0  = blockIdx.y * 32;
    // load: thread.x sweeps hb (stride-6 reads), rows = node
    for (int yy = threadIdx.y; yy < 32; yy += 8) {
        int node = n0 + yy;
        int hb   = hb0 + threadIdx.x;
        float2 v = make_float2(0.f, 0.f);
        if (node < N_NODE && hb < N_HID * N_BAT) {
            const float* s = ext + ((size_t)node * (N_HID * N_BAT) + hb) * N_IN;
            v.x = s[0]; v.y = s[1];
        }
        tile[yy][threadIdx.x] = v;
    }
    __syncthreads();
    // store: thread.x sweeps node (coalesced float2 writes)
    for (int yy = threadIdx.y; yy < 32; yy += 8) {
        int hb   = hb0 + yy;
        int node = n0 + threadIdx.x;
        if (node < N_NODE && hb < N_HID * N_BAT) {
            *(float2*)&g_noise[((size_t)hb * N_NODE + node) * 2] = tile[threadIdx.x][yy];
        }
    }
}

// ---------------- simulation helpers ----------------
__device__ __forceinline__ float h_tf_dev(float a, float b, float d, float z) {
    float u   = fmaf(a, z, -b);
    float num = 1e-5f + fabsf(u);
    float den = fmaf(1e-5f, d, fabsf(1.0f - __expf(-d * u)));
    return __fdividef(num, den);
}

__device__ __forceinline__ float tanh_pos(float y) {
    float t = __expf(-2.f * y);
    return __fdividef(1.f - t, 1.f + t);
}

#define FMA2(acc, a, b) \
    asm("fma.rn.f32x2 %0, %1, %2, %0;" : "+l"(acc) : "l"(a), "l"(b))

__global__ void __launch_bounds__(NTH, 1) sim_kernel(
    const float* __restrict__ ext,   // original (200,1500,20,6) — only for BOLD n2
    const float* __restrict__ hx,    // (200,6)
    float* __restrict__ out,         // (200,20)
    const float* gp, const float* gEEp, const float* gIEp,
    const float* gEIp, const float* stdp)
{
    __shared__ __align__(16) float Ebuf[2][224];     // E padded to 224, pads = 0
    __shared__ __align__(16) float AccP[16 * RS];    // 16 class-partials per row-slot

    const int tid = threadIdx.x;
    const int w   = tid >> 5;
    const int l   = tid & 31;
    const int rbase = w * 25;                        // rows 25w..25w+24
    const int sbase = w * 26;                        // Acc slot base (even, pad slot 25)

    // ---- W registers: 12 row-pairs + 1 single row, 7 interleaved cols/lane ----
    unsigned long long W2[12][7];
    float Ws[7];
#pragma unroll
    for (int jp = 0; jp < 12; jp++) {
        int r0 = rbase + 2 * jp;
#pragma unroll
        for (int j = 0; j < 7; j++) {
            int col = l + 32 * j;
            float w0 = (col < N_NODE) ? g_ls[r0 * N_NODE + col] : 0.f;
            float w1 = (col < N_NODE) ? g_ls[(r0 + 1) * N_NODE + col] : 0.f;
            asm("mov.b64 %0, {%1, %2};" : "=l"(W2[jp][j]) : "f"(w0), "f"(w1));
        }
    }
#pragma unroll
    for (int j = 0; j < 7; j++) {
        int col = l + 32 * j;
        Ws[j] = (col < N_NODE) ? g_ls[(rbase + 24) * N_NODE + col] : 0.f;
    }

    const float gg   = *gp;
    const float cEE  = 0.001f + fmaxf(*gEEp, 0.f);
    const float cIE  = 0.001f + fmaxf(*gIEp, 0.f);
    const float cEI  = 0.001f + fmaxf(*gEIp, 0.f);
    const float s_in = 0.02f + fmaxf(*stdp, 0.f);
    const float nscl = 0.70710678118654752440f * s_in;
    const float ln066 = -0.41551544396166582194f;
    const float it0  = 0.5f / 0.98f;
    const float its  = 1.f / 0.65f;
    const float itf  = 1.f / 0.41f;
    const float irho = 1.f / 0.34f;

    const bool tail  = (tid < N_NODE);
    const int  aslot = (tid / 25) * 26 + (tid % 25); // this node's Acc slot

    float E = 0.f, I = 0.f, X = 0.f, F = 0.f, V = 0.f, Q = 0.f, vpow = 0.f;

    // zero E buffers (pads must be 0)
    for (int i = tid; i < 2 * 224; i += NTH) ((float*)Ebuf)[i] = 0.f;
    __syncthreads();

    if (tail) {
        E = hx[tid * 6 + 0];
        I = hx[tid * 6 + 1];
        X = hx[tid * 6 + 2];
        F = hx[tid * 6 + 3];
        V = hx[tid * 6 + 4];
        Q = hx[tid * 6 + 5];
        vpow = __expf(3.125f * __logf(V));
        Ebuf[0][tid] = E;
    }
    __syncthreads();

    float* curE = Ebuf[0];
    float* nxtE = Ebuf[1];

#pragma unroll 1
    for (int b = 0; b < N_BAT; b++) {
        // noise offset for (h, b): ((h*20+b)*200 + tid)*2
        const float* np = g_noise + ((size_t)b * N_NODE + tid) * 2;
        float nx = 0.f, ny = 0.f;
        if (tail) {                                  // exposed once per batch
            float2 t0 = *(const float2*)np;
            nx = t0.x; ny = t0.y;
        }
#pragma unroll 1
        for (int h = 0; h < N_HID; h++) {
            // ---- prefetch next step's noise (coalesced, covered by phase A) ----
            float pnx = 0.f, pny = 0.f;
            const float* npn = np + (size_t)N_BAT * N_NODE * 2;  // h+1 same b
            if (tail && h + 1 < N_HID) {
                float2 t1 = *(const float2*)npn;
                pnx = t1.x; pny = t1.y;
            }

            // -------- phase A: column-interleaved matvec ------------------------
            float e[7];
#pragma unroll
            for (int j = 0; j < 7; j++) e[j] = curE[l + 32 * j];
            unsigned long long ed[7];
#pragma unroll
            for (int j = 0; j < 7; j++)
                asm("mov.b64 %0, {%1, %1};" : "=l"(ed[j]) : "f"(e[j]));

            float p[25];
#pragma unroll
            for (int jp = 0; jp < 12; jp++) {
                unsigned long long acc = 0ull;
#pragma unroll
                for (int j = 0; j < 7; j++) FMA2(acc, W2[jp][j], ed[j]);
                asm("mov.b64 {%0, %1}, %2;" : "=f"(p[2 * jp]), "=f"(p[2 * jp + 1]) : "l"(acc));
            }
            {
                float ps = 0.f;
#pragma unroll
                for (int j = 0; j < 7; j++) ps = fmaf(Ws[j], e[j], ps);
                p[24] = ps;
            }

            // ---- cross-lane: one butterfly stage -> 16 class-partials ----------
#pragma unroll
            for (int i = 0; i < 25; i++)
                p[i] += __shfl_xor_sync(0xffffffffu, p[i], 16);

            if (l < 16) {                            // lanes 16-31 hold duplicates
                float* ap = &AccP[l * RS + sbase];
#pragma unroll
                for (int jp = 0; jp < 12; jp++)
                    *(float2*)&ap[2 * jp] = make_float2(p[2 * jp], p[2 * jp + 1]);
                ap[24] = p[24];
            }
            __syncthreads();                         // bar1: partials published

            // -------- phase B: tail threads --------------------------------------
            if (tail) {
                float a0 = 0.f, a1 = 0.f, a2 = 0.f, a3 = 0.f;
#pragma unroll
                for (int c = 0; c < 16; c += 4) {
                    a0 += AccP[(c + 0) * RS + aslot];
                    a1 += AccP[(c + 1) * RS + aslot];
                    a2 += AccP[(c + 2) * RS + aslot];
                    a3 += AccP[(c + 3) * RS + aslot];
                }
                float acc = gg * ((a0 + a1) + (a2 + a3));

                float Eold = E, Iold = I;
                float IE = fmaxf(acc + fmaf(cEE, Eold, 0.32f) - cIE * Iold, 0.f);
                float II = fmaxf(fmaf(cEI, Eold, 0.224f) - Iold, 0.f);
                float rE = h_tf_dev(310.f, 125.f, 0.16f,  IE);
                float rI = h_tf_dev(615.f, 177.f, 0.087f, II);
                float En = Eold + 0.5f * fmaf(0.000641f * (1.f - Eold), rE, -0.01f * Eold)
                                + nscl * nx;
                float In = Iold + 0.5f * fmaf(0.001f, rI, -0.1f * Iold)
                                + nscl * ny;
                E = tanh_pos(1e-5f + fmaxf(En, 0.f));
                I = tanh_pos(1e-5f + fmaxf(In, 0.f));
                nxtE[tid] = E;

                // deferred hemodynamics for step h-1 (independent chain, ILP-overlaps E/I)
                if (h > 0) {
                    X = X + 0.5f * (Eold - X * its - (F - 1.f) * itf);
                    F = F + 0.5f * X;
                    float Vn = fmaf(it0, F - vpow, V);
                    float vq = __expf(3.125f * __logf(Vn));
                    float qa = F * (1.f - __expf(__fdividef(ln066, F))) * irho;
                    float qb = __fdividef(Q * vq, Vn);
                    Q = fmaf(it0, qa - qb, Q);
                    V = Vn; vpow = vq;
                }
            }
            __syncthreads();                         // bar2: nxtE ready
            float* t2 = curE; curE = nxtE; nxtE = t2;
            nx = pnx; ny = pny; np = npn;
        }

        // -------- batch end: flush lagging hemo + emit BOLD ----------------------
        if (tail) {
            float Eold = E;
            X = X + 0.5f * (Eold - X * its - (F - 1.f) * itf);
            F = F + 0.5f * X;
            float Vn = fmaf(it0, F - vpow, V);
            float vq = __expf(3.125f * __logf(Vn));
            float qa = F * (1.f - __expf(__fdividef(ln066, F))) * irho;
            float qb = __fdividef(Q * vq, Vn);
            Q = fmaf(it0, qa - qb, Q);
            V = Vn; vpow = vq;

            float n2 = ext[((size_t)(tid * N_HID + (N_HID - 1)) * N_BAT + b) * N_IN + 2];
            float bold = 0.02f * n2 +
                5.8823529411764705882f * (2.38f * (1.f - Q)
                                        + 2.f * (1.f - __fdividef(Q, V))
                                        + 0.48f * (1.f - V));
            out[tid * N_BAT + b] = bold;
        }
    }
}

// ---------------- launch ----------------
extern "C" void kernel_launch(void* const* d_in, const int* in_sizes, int n_in,
                              void* d_out, int out_size) {
    const float* ext  = (const float*)d_in[0];  // external (200,1500,20,6)
    const float* hx   = (const float*)d_in[1];  // hx (200,6)
    // d_in[2] = hE (unused by reference)
    const float* sc   = (const float*)d_in[3];  // sc (200,200)
    const float* wbb  = (const float*)d_in[4];  // w_bb (200,200)
    const float* gp   = (const float*)d_in[5];
    const float* gEE  = (const float*)d_in[6];
    const float* gIE  = (const float*)d_in[7];
    const float* gEI  = (const float*)d_in[8];
    const float* stdp = (const float*)d_in[9];
    float* out = (float*)d_out;

    prep1_kernel<<<N_NODE, 256>>>(sc, wbb);
    prep2_kernel<<<1, 256>>>();
    prep3_kernel<<<1, 256>>>();  // (gridDim fixed below)
    // NOTE: prep3 needs one block per row
    prep3_kernel<<<N_NODE, 256>>>();
    {
        dim3 grid((N_HID * N_BAT + 31) / 32, (N_NODE + 31) / 32);
        dim3 blk(32, 8);
        transpose_noise_kernel<<<grid, blk>>>(ext);
    }
    sim_kernel<<<1, NTH>>>(ext, hx, out, gp, gEE, gIE, gEI, stdp);
}